// round 1
// baseline (speedup 1.0000x reference)
#include <cuda_runtime.h>
#include <cuda_bf16.h>

// GramsEmbedding: out[b,s,:] = sum over UNIQUE gram indices of weight[idx,:].
// K_GRAMS=2, BATCH=2, SEQ=1024, EMBED_DIM=128, NUM_CLASSES=32000.
// input: int32 [2, 2, 1024]  (d_in[0])
// weight: fp32 [32000, 128]  (d_in[1])
// out: fp32 [2, 1024, 128]
//
// n_hot uses scatter-SET (union) semantics: if idx0 == idx1 the row is counted ONCE.

static constexpr int NUM_POS   = 2 * 1024;   // B * S
static constexpr int EMBED_DIM = 128;
static constexpr int VEC       = 4;          // float4
static constexpr int VPR       = EMBED_DIM / VEC;  // 32 float4 per row

__global__ void grams_embedding_kernel(const int* __restrict__ idx,
                                       const float* __restrict__ weight,
                                       float* __restrict__ out) {
    // One thread per float4 of output. gid in [0, NUM_POS * VPR)
    int gid = blockIdx.x * blockDim.x + threadIdx.x;
    if (gid >= NUM_POS * VPR) return;

    int p = gid >> 5;          // position index (gid / VPR), VPR = 32
    int v = gid & (VPR - 1);   // float4 lane within the embedding row

    int i0 = __ldg(idx + p);            // gram 0: input[0, b, s]
    int i1 = __ldg(idx + NUM_POS + p);  // gram 1: input[1, b, s]

    const float4* w = reinterpret_cast<const float4*>(weight);
    float4 a = __ldg(w + (long)i0 * VPR + v);

    float4 r = a;
    if (i1 != i0) {
        float4 b = __ldg(w + (long)i1 * VPR + v);
        r.x += b.x; r.y += b.y; r.z += b.z; r.w += b.w;
    }

    reinterpret_cast<float4*>(out)[gid] = r;
}

extern "C" void kernel_launch(void* const* d_in, const int* in_sizes, int n_in,
                              void* d_out, int out_size) {
    const int*   idx    = (const int*)d_in[0];
    const float* weight = (const float*)d_in[1];
    float*       out    = (float*)d_out;

    int total = NUM_POS * VPR;            // 65536 threads
    int threads = 256;
    int blocks = (total + threads - 1) / threads;  // 256 blocks
    grams_embedding_kernel<<<blocks, threads>>>(idx, weight, out);
}

// round 2
// speedup vs baseline: 1.0165x; 1.0165x over previous
#include <cuda_runtime.h>
#include <cuda_bf16.h>

// GramsEmbedding: out[b,s,:] = sum over UNIQUE gram indices of weight[idx,:].
// K_GRAMS=2, BATCH=2, SEQ=1024, EMBED_DIM=128, NUM_CLASSES=32000.
// input: int32 [2, 2, 1024]  (d_in[0])
// weight: fp32 [32000, 128]  (d_in[1])
// out: fp32 [2, 1024, 128]
//
// n_hot uses scatter-SET (union) semantics: if idx0 == idx1 the row is counted ONCE.

static constexpr int NUM_POS   = 2 * 1024;   // B * S
static constexpr int EMBED_DIM = 128;
static constexpr int VEC       = 4;          // float4
static constexpr int VPR       = EMBED_DIM / VEC;  // 32 float4 per row

__global__ void grams_embedding_kernel(const int* __restrict__ idx,
                                       const float* __restrict__ weight,
                                       float* __restrict__ out) {
    // One thread per float4 of output. gid in [0, NUM_POS * VPR)
    int gid = blockIdx.x * blockDim.x + threadIdx.x;
    if (gid >= NUM_POS * VPR) return;

    int p = gid >> 5;          // position index (gid / VPR), VPR = 32
    int v = gid & (VPR - 1);   // float4 lane within the embedding row

    int i0 = __ldg(idx + p);            // gram 0: input[0, b, s]
    int i1 = __ldg(idx + NUM_POS + p);  // gram 1: input[1, b, s]

    const float4* w = reinterpret_cast<const float4*>(weight);
    float4 a = __ldg(w + (long)i0 * VPR + v);

    float4 r = a;
    if (i1 != i0) {
        float4 b = __ldg(w + (long)i1 * VPR + v);
        r.x += b.x; r.y += b.y; r.z += b.z; r.w += b.w;
    }

    reinterpret_cast<float4*>(out)[gid] = r;
}

extern "C" void kernel_launch(void* const* d_in, const int* in_sizes, int n_in,
                              void* d_out, int out_size) {
    const int*   idx    = (const int*)d_in[0];
    const float* weight = (const float*)d_in[1];
    float*       out    = (float*)d_out;

    int total = NUM_POS * VPR;            // 65536 threads
    int threads = 256;
    int blocks = (total + threads - 1) / threads;  // 256 blocks
    grams_embedding_kernel<<<blocks, threads>>>(idx, weight, out);
}